// round 13
// baseline (speedup 1.0000x reference)
#include <cuda_runtime.h>

// Decoder_21225728377092 — R6 champion (94.5us) restored byte-for-byte, with
// ONE isolated delta: per-warp phase-staggered FFN f-loop start (warp*8,
// mask-wrapped) to decorrelate LDS/FMA pipe bursts across same-SMSP warps.
//
// Math identity: softmax over seq of a seq-constant tensor is uniform 1/4096,
// so attention out = teo/4096, teo = q^2 - k*v, k from s-1 (clamp 0),
// v from s+1 (clamp SEQ-1). 8 mha stages -> seq radius 8 -> per-warp halo 8.

#define L    4
#define D    6
#define DFF  64
#define SEQ  4096
#define NB   128
#define P    8
#define INT_W 240                 // interior positions per warp (256 - 16 halo)
#define WPR  18                   // warps per row: 18*240 >= 4096
#define WPB  8
#define TPB  (WPB * 32)           // 256
#define NBLK ((NB * WPR) / WPB)   // 288 blocks, single wave
#define EPSF 1e-6f
#define INV_S (1.0f / 4096.0f)
#define FULL 0xffffffffu

typedef unsigned long long u64;

__device__ __forceinline__ u64 pk(float a, float b) {
    u64 r; asm("mov.b64 %0, {%1,%2};" : "=l"(r) : "f"(a), "f"(b)); return r;
}
__device__ __forceinline__ float2 up(u64 v) {
    float2 r; asm("mov.b64 {%0,%1}, %2;" : "=f"(r.x), "=f"(r.y) : "l"(v)); return r;
}
__device__ __forceinline__ u64 f2fma(u64 a, u64 b, u64 c) {
    u64 d; asm("fma.rn.f32x2 %0,%1,%2,%3;" : "=l"(d) : "l"(a), "l"(b), "l"(c)); return d;
}
__device__ __forceinline__ u64 f2mul(u64 a, u64 b) {
    u64 d; asm("mul.rn.f32x2 %0,%1,%2;" : "=l"(d) : "l"(a), "l"(b)); return d;
}
__device__ __forceinline__ u64 f2add(u64 a, u64 b) {
    u64 d; asm("add.rn.f32x2 %0,%1,%2;" : "=l"(d) : "l"(a), "l"(b)); return d;
}
__device__ __forceinline__ u64 relu2(u64 v) {
    float2 t = up(v);
    return pk(fmaxf(t.x, 0.0f), fmaxf(t.y, 0.0f));
}

struct Smem {
    u64 w1p[L][DFF][8];     // [l][f][0..5]=w1 pairs, [6]=b1 pair, [7] pad
    u64 w2p[L][DFF][8];     // [l][f][0..5]=w2[l][d][f] pairs
    u64 attp[2 * L][D][8];  // [stage][d][qw qb kw kb vwn vbn lnw lnb]
    u64 ffnlnp[L][2][8];    // [l][w|b][d]
    u64 decp[2][8];         // [w|b][d]
    u64 b2p[L][8];          // [l][d]
};

// packed layernorm over D=6 on one position-pair; weight/bias stride S (u64s)
template <int S>
__device__ __forceinline__ void ln6p(u64* v, const u64* w, const u64* b) {
    u64 s  = f2add(f2add(f2add(v[0], v[1]), f2add(v[2], v[3])), f2add(v[4], v[5]));
    u64 ss = f2mul(v[0], v[0]);
#pragma unroll
    for (int d = 1; d < D; d++) ss = f2fma(v[d], v[d], ss);
    float2 sf = up(s), ssf = up(ss);
    float mux = sf.x * (1.0f / 6.0f), muy = sf.y * (1.0f / 6.0f);
    float varx = fmaf(ssf.x, 1.0f / 6.0f, -mux * mux);
    float vary = fmaf(ssf.y, 1.0f / 6.0f, -muy * muy);
    float rx = rsqrtf(varx + EPSF);
    float ry = rsqrtf(vary + EPSF);
    u64 rp    = pk(rx, ry);
    u64 nmurp = pk(-mux * rx, -muy * ry);
#pragma unroll
    for (int d = 0; d < D; d++) {
        u64 t = f2fma(v[d], rp, nmurp);       // (v - mu) * r
        v[d] = f2fma(t, w[d * S], b[d * S]);  // * w + b
    }
}

__global__ __launch_bounds__(TPB, 2) void decoder_fused_kernel(
    const float* __restrict__ g_x,
    const float* __restrict__ g_dec_w, const float* __restrict__ g_dec_b,
    const float* __restrict__ g_qw, const float* __restrict__ g_qb,
    const float* __restrict__ g_kw, const float* __restrict__ g_kb,
    const float* __restrict__ g_vw, const float* __restrict__ g_vb,
    const float* __restrict__ g_mlw, const float* __restrict__ g_mlb,
    const float* __restrict__ g_w1, const float* __restrict__ g_b1,
    const float* __restrict__ g_w2, const float* __restrict__ g_b2,
    const float* __restrict__ g_flw, const float* __restrict__ g_flb,
    float* __restrict__ g_out)
{
    __shared__ Smem sm;
    const int tid  = threadIdx.x;
    const int lane = tid & 31;
    const int warp = tid >> 5;

    // ---------------- global warp -> (row, tile) ----------------
    const unsigned g = (unsigned)blockIdx.x * WPB + warp;
    const unsigned row = g / WPR;
    const unsigned w   = g - row * WPR;
    const int istart = min((int)w * INT_W, SEQ - INT_W);
    const int s0 = istart - 8 + P * lane;

    // ---------------- load my 8 positions ----------------
    const float* xbase = g_x + (size_t)row * SEQ * D;
    float t[P * D];
    if (s0 >= 0 && s0 <= SEQ - P) {
        const float4* p = reinterpret_cast<const float4*>(xbase + (size_t)s0 * D);
#pragma unroll
        for (int k = 0; k < P * D / 4; k++) reinterpret_cast<float4*>(t)[k] = p[k];
    } else {
#pragma unroll
        for (int i = 0; i < P; i++) {
            int sc = min(max(s0 + i, 0), SEQ - 1);
            const float2* p = reinterpret_cast<const float2*>(xbase + (size_t)sc * D);
            float2 a0 = p[0], a1 = p[1], a2 = p[2];
            t[i * D + 0] = a0.x; t[i * D + 1] = a0.y; t[i * D + 2] = a1.x;
            t[i * D + 3] = a1.y; t[i * D + 4] = a2.x; t[i * D + 5] = a2.y;
        }
    }

    // ---------------- weight staging (packed broadcast pairs) ----------------
    for (int i = tid; i < L * DFF * D; i += TPB) {
        int l = i / (DFF * D), f = (i / D) % DFF, d = i % D;
        float v = g_w1[i];
        sm.w1p[l][f][d] = pk(v, v);
    }
    for (int i = tid; i < L * DFF; i += TPB) {
        float v = g_b1[i];
        sm.w1p[i / DFF][i % DFF][6] = pk(v, v);
    }
    for (int i = tid; i < L * D * DFF; i += TPB) {
        int l = i / (D * DFF), d = (i / DFF) % D, f = i % DFF;
        float v = g_w2[i];
        sm.w2p[l][f][d] = pk(v, v);
    }
    for (int i = tid; i < 2 * L * D; i += TPB) {
        int la = i / D, d = i % D;
        sm.attp[la][d][0] = pk(g_qw[i], g_qw[i]);
        sm.attp[la][d][1] = pk(g_qb[i], g_qb[i]);
        sm.attp[la][d][2] = pk(g_kw[i], g_kw[i]);
        sm.attp[la][d][3] = pk(g_kb[i], g_kb[i]);
        sm.attp[la][d][4] = pk(-g_vw[i], -g_vw[i]);   // negated
        sm.attp[la][d][5] = pk(-g_vb[i], -g_vb[i]);   // negated
        sm.attp[la][d][6] = pk(g_mlw[i], g_mlw[i]);
        sm.attp[la][d][7] = pk(g_mlb[i], g_mlb[i]);
    }
    for (int i = tid; i < L * D; i += TPB) {
        int l = i / D, d = i % D;
        sm.ffnlnp[l][0][d] = pk(g_flw[i], g_flw[i]);
        sm.ffnlnp[l][1][d] = pk(g_flb[i], g_flb[i]);
        sm.b2p[l][d] = pk(g_b2[i], g_b2[i]);
    }
    if (tid < D) {
        sm.decp[0][tid] = pk(g_dec_w[tid], g_dec_w[tid]);
        sm.decp[1][tid] = pk(g_dec_b[tid], g_dec_b[tid]);
    }
    __syncthreads();

    // ---------------- packed state: xp[j][d] = (pos 2j, pos 2j+1) ----------
    u64 xp[4][D];
#pragma unroll
    for (int j = 0; j < 4; j++)
#pragma unroll
        for (int d = 0; d < D; d++)
            xp[j][d] = pk(t[(2 * j) * D + d], t[(2 * j + 1) * D + d]);

#pragma unroll
    for (int j = 0; j < 4; j++) ln6p<1>(&xp[j][0], &sm.decp[0][0], &sm.decp[1][0]);

    const bool edgeL = (s0 == 0);
    const bool edgeR = (s0 == SEQ - P);
    const u64 INV2 = pk(INV_S, INV_S);
    const int foff = (warp & 7) * 8;   // per-warp FFN phase stagger

#pragma unroll 1
    for (int l = 0; l < L; l++) {
        // -------- two attention+LN stages --------
#pragma unroll
        for (int a = 0; a < 2; a++) {
            const int la = l * 2 + a;
#pragma unroll
            for (int d = 0; d < D; d++) {
                float2 p0 = up(xp[0][d]);
                float2 p1 = up(xp[1][d]);
                float2 p2 = up(xp[2][d]);
                float2 p3 = up(xp[3][d]);
                float xm1 = __shfl_up_sync(FULL, p3.y, 1);
                float xq1 = __shfl_down_sync(FULL, p0.x, 1);
                if (edgeL) xm1 = p0.x;
                if (edgeR) xq1 = p3.y;
                u64 l0 = pk(xm1, p0.x);
                u64 l1 = pk(p0.y, p1.x);   // also v-in for pair 0
                u64 l2 = pk(p1.y, p2.x);   // also v-in for pair 1
                u64 l3 = pk(p2.y, p3.x);   // also v-in for pair 2
                u64 r3 = pk(p3.y, xq1);    // v-in for pair 3
                const u64* wd = &sm.attp[la][d][0];
                ulonglong2 wq = *reinterpret_cast<const ulonglong2*>(wd + 0); // qw qb
                ulonglong2 wk = *reinterpret_cast<const ulonglong2*>(wd + 2); // kw kb
                ulonglong2 wv = *reinterpret_cast<const ulonglong2*>(wd + 4); // -vw -vb
                u64 q0 = f2fma(xp[0][d], wq.x, wq.y);
                u64 q1 = f2fma(xp[1][d], wq.x, wq.y);
                u64 q2 = f2fma(xp[2][d], wq.x, wq.y);
                u64 q3 = f2fma(xp[3][d], wq.x, wq.y);
                u64 k0 = f2fma(l0, wk.x, wk.y);
                u64 k1 = f2fma(l1, wk.x, wk.y);
                u64 k2 = f2fma(l2, wk.x, wk.y);
                u64 k3 = f2fma(l3, wk.x, wk.y);
                u64 n0 = f2fma(l1, wv.x, wv.y);   // -v
                u64 n1 = f2fma(l2, wv.x, wv.y);
                u64 n2 = f2fma(l3, wv.x, wv.y);
                u64 n3 = f2fma(r3, wv.x, wv.y);
                // teo = q^2 - k*v; x += teo/S with shallow x-chain
                u64 t0 = f2fma(q0, q0, f2mul(k0, n0));
                u64 t1 = f2fma(q1, q1, f2mul(k1, n1));
                u64 t2 = f2fma(q2, q2, f2mul(k2, n2));
                u64 t3 = f2fma(q3, q3, f2mul(k3, n3));
                xp[0][d] = f2fma(t0, INV2, xp[0][d]);
                xp[1][d] = f2fma(t1, INV2, xp[1][d]);
                xp[2][d] = f2fma(t2, INV2, xp[2][d]);
                xp[3][d] = f2fma(t3, INV2, xp[3][d]);
            }
#pragma unroll
            for (int j = 0; j < 4; j++)
                ln6p<8>(&xp[j][0], &sm.attp[la][0][6], &sm.attp[la][0][7]);
        }

        // -------- FFN: broadcast-LDS pair weights, phase-staggered f order --
        u64 y[4][D];
#pragma unroll
        for (int j = 0; j < 4; j++)
#pragma unroll
            for (int d = 0; d < D; d++)
                y[j][d] = f2add(xp[j][d], sm.b2p[l][d]);

        const u64* w1r = &sm.w1p[l][0][0];
        const u64* w2r = &sm.w2p[l][0][0];
#pragma unroll 4
        for (int f = 0; f < DFF; f++) {
            const int fi = (f + foff) & (DFF - 1);
            ulonglong2 wa = *reinterpret_cast<const ulonglong2*>(w1r + fi * 8 + 0);
            ulonglong2 wb = *reinterpret_cast<const ulonglong2*>(w1r + fi * 8 + 2);
            ulonglong2 wc = *reinterpret_cast<const ulonglong2*>(w1r + fi * 8 + 4);
            u64 b1 = w1r[fi * 8 + 6];
            u64 h0 = f2fma(xp[0][0], wa.x, b1);
            u64 h1 = f2fma(xp[1][0], wa.x, b1);
            u64 h2 = f2fma(xp[2][0], wa.x, b1);
            u64 h3 = f2fma(xp[3][0], wa.x, b1);
            h0 = f2fma(xp[0][1], wa.y, h0); h1 = f2fma(xp[1][1], wa.y, h1);
            h2 = f2fma(xp[2][1], wa.y, h2); h3 = f2fma(xp[3][1], wa.y, h3);
            h0 = f2fma(xp[0][2], wb.x, h0); h1 = f2fma(xp[1][2], wb.x, h1);
            h2 = f2fma(xp[2][2], wb.x, h2); h3 = f2fma(xp[3][2], wb.x, h3);
            h0 = f2fma(xp[0][3], wb.y, h0); h1 = f2fma(xp[1][3], wb.y, h1);
            h2 = f2fma(xp[2][3], wb.y, h2); h3 = f2fma(xp[3][3], wb.y, h3);
            h0 = f2fma(xp[0][4], wc.x, h0); h1 = f2fma(xp[1][4], wc.x, h1);
            h2 = f2fma(xp[2][4], wc.x, h2); h3 = f2fma(xp[3][4], wc.x, h3);
            h0 = f2fma(xp[0][5], wc.y, h0); h1 = f2fma(xp[1][5], wc.y, h1);
            h2 = f2fma(xp[2][5], wc.y, h2); h3 = f2fma(xp[3][5], wc.y, h3);
            h0 = relu2(h0); h1 = relu2(h1); h2 = relu2(h2); h3 = relu2(h3);
            ulonglong2 va = *reinterpret_cast<const ulonglong2*>(w2r + fi * 8 + 0);
            ulonglong2 vb = *reinterpret_cast<const ulonglong2*>(w2r + fi * 8 + 2);
            ulonglong2 vc = *reinterpret_cast<const ulonglong2*>(w2r + fi * 8 + 4);
            y[0][0] = f2fma(h0, va.x, y[0][0]); y[1][0] = f2fma(h1, va.x, y[1][0]);
            y[2][0] = f2fma(h2, va.x, y[2][0]); y[3][0] = f2fma(h3, va.x, y[3][0]);
            y[0][1] = f2fma(h0, va.y, y[0][1]); y[1][1] = f2fma(h1, va.y, y[1][1]);
            y[2][1] = f2fma(h2, va.y, y[2][1]); y[3][1] = f2fma(h3, va.y, y[3][1]);
            y[0][2] = f2fma(h0, vb.x, y[0][2]); y[1][2] = f2fma(h1, vb.x, y[1][2]);
            y[2][2] = f2fma(h2, vb.x, y[2][2]); y[3][2] = f2fma(h3, vb.x, y[3][2]);
            y[0][3] = f2fma(h0, vb.y, y[0][3]); y[1][3] = f2fma(h1, vb.y, y[1][3]);
            y[2][3] = f2fma(h2, vb.y, y[2][3]); y[3][3] = f2fma(h3, vb.y, y[3][3]);
            y[0][4] = f2fma(h0, vc.x, y[0][4]); y[1][4] = f2fma(h1, vc.x, y[1][4]);
            y[2][4] = f2fma(h2, vc.x, y[2][4]); y[3][4] = f2fma(h3, vc.x, y[3][4]);
            y[0][5] = f2fma(h0, vc.y, y[0][5]); y[1][5] = f2fma(h1, vc.y, y[1][5]);
            y[2][5] = f2fma(h2, vc.y, y[2][5]); y[3][5] = f2fma(h3, vc.y, y[3][5]);
        }
#pragma unroll
        for (int j = 0; j < 4; j++) {
            ln6p<1>(&y[j][0], &sm.ffnlnp[l][0][0], &sm.ffnlnp[l][1][0]);
#pragma unroll
            for (int d = 0; d < D; d++) xp[j][d] = y[j][d];
        }
    }

    // ---------------- write interior (lanes 1..30) ----------------
    if (lane >= 1 && lane < 31) {
#pragma unroll
        for (int j = 0; j < 4; j++)
#pragma unroll
            for (int d = 0; d < D; d++) {
                float2 v = up(xp[j][d]);
                t[(2 * j) * D + d] = v.x;
                t[(2 * j + 1) * D + d] = v.y;
            }
        float4* o = reinterpret_cast<float4*>(g_out + ((size_t)row * SEQ + s0) * D);
#pragma unroll
        for (int k = 0; k < P * D / 4; k++) o[k] = reinterpret_cast<float4*>(t)[k];
    }
}

extern "C" void kernel_launch(void* const* d_in, const int* in_sizes, int n_in,
                              void* d_out, int out_size) {
    decoder_fused_kernel<<<NBLK, TPB>>>(
        (const float*)d_in[0],
        (const float*)d_in[2],  (const float*)d_in[3],
        (const float*)d_in[4],  (const float*)d_in[5],
        (const float*)d_in[6],  (const float*)d_in[7],
        (const float*)d_in[8],  (const float*)d_in[9],
        (const float*)d_in[12], (const float*)d_in[13],
        (const float*)d_in[14], (const float*)d_in[15],
        (const float*)d_in[16], (const float*)d_in[17],
        (const float*)d_in[18], (const float*)d_in[19],
        (float*)d_out);
}

// round 14
// speedup vs baseline: 1.0502x; 1.0502x over previous
#include <cuda_runtime.h>

// Decoder_21225728377092 — FINAL: R6 champion (94.5us) restored byte-for-byte.
// Fused single kernel, warp-self-contained tiles, packed f32x2 math,
// 8 positions/thread, per-d attention weight rows, negated v-weights,
// 288x256 single-wave launch.
//
// Math identity: softmax over seq of a seq-constant tensor is uniform 1/4096,
// so attention out = teo/4096, teo = q^2 - k*v, k from s-1 (clamp 0),
// v from s+1 (clamp SEQ-1). 8 mha stages -> seq radius 8 -> per-warp halo 8.

#define L    4
#define D    6
#define DFF  64
#define SEQ  4096
#define NB   128
#define P    8
#define INT_W 240                 // interior positions per warp (256 - 16 halo)
#define WPR  18                   // warps per row: 18*240 >= 4096
#define WPB  8
#define TPB  (WPB * 32)           // 256
#define NBLK ((NB * WPR) / WPB)   // 288 blocks, single wave
#define EPSF 1e-6f
#define INV_S (1.0f / 4096.0f)
#define FULL 0xffffffffu

typedef unsigned long long u64;

__device__ __forceinline__ u64 pk(float a, float b) {
    u64 r; asm("mov.b64 %0, {%1,%2};" : "=l"(r) : "f"(a), "f"(b)); return r;
}
__device__ __forceinline__ float2 up(u64 v) {
    float2 r; asm("mov.b64 {%0,%1}, %2;" : "=f"(r.x), "=f"(r.y) : "l"(v)); return r;
}
__device__ __forceinline__ u64 f2fma(u64 a, u64 b, u64 c) {
    u64 d; asm("fma.rn.f32x2 %0,%1,%2,%3;" : "=l"(d) : "l"(a), "l"(b), "l"(c)); return d;
}
__device__ __forceinline__ u64 f2mul(u64 a, u64 b) {
    u64 d; asm("mul.rn.f32x2 %0,%1,%2;" : "=l"(d) : "l"(a), "l"(b)); return d;
}
__device__ __forceinline__ u64 f2add(u64 a, u64 b) {
    u64 d; asm("add.rn.f32x2 %0,%1,%2;" : "=l"(d) : "l"(a), "l"(b)); return d;
}
__device__ __forceinline__ u64 relu2(u64 v) {
    float2 t = up(v);
    return pk(fmaxf(t.x, 0.0f), fmaxf(t.y, 0.0f));
}

struct Smem {
    u64 w1p[L][DFF][8];     // [l][f][0..5]=w1 pairs, [6]=b1 pair, [7] pad
    u64 w2p[L][DFF][8];     // [l][f][0..5]=w2[l][d][f] pairs
    u64 attp[2 * L][D][8];  // [stage][d][qw qb kw kb vwn vbn lnw lnb]
    u64 ffnlnp[L][2][8];    // [l][w|b][d]
    u64 decp[2][8];         // [w|b][d]
    u64 b2p[L][8];          // [l][d]
};

// packed layernorm over D=6 on one position-pair; weight/bias stride S (u64s)
template <int S>
__device__ __forceinline__ void ln6p(u64* v, const u64* w, const u64* b) {
    u64 s  = f2add(f2add(f2add(v[0], v[1]), f2add(v[2], v[3])), f2add(v[4], v[5]));
    u64 ss = f2mul(v[0], v[0]);
#pragma unroll
    for (int d = 1; d < D; d++) ss = f2fma(v[d], v[d], ss);
    float2 sf = up(s), ssf = up(ss);
    float mux = sf.x * (1.0f / 6.0f), muy = sf.y * (1.0f / 6.0f);
    float varx = fmaf(ssf.x, 1.0f / 6.0f, -mux * mux);
    float vary = fmaf(ssf.y, 1.0f / 6.0f, -muy * muy);
    float rx = rsqrtf(varx + EPSF);
    float ry = rsqrtf(vary + EPSF);
    u64 rp    = pk(rx, ry);
    u64 nmurp = pk(-mux * rx, -muy * ry);
#pragma unroll
    for (int d = 0; d < D; d++) {
        u64 t = f2fma(v[d], rp, nmurp);       // (v - mu) * r
        v[d] = f2fma(t, w[d * S], b[d * S]);  // * w + b
    }
}

__global__ __launch_bounds__(TPB, 2) void decoder_fused_kernel(
    const float* __restrict__ g_x,
    const float* __restrict__ g_dec_w, const float* __restrict__ g_dec_b,
    const float* __restrict__ g_qw, const float* __restrict__ g_qb,
    const float* __restrict__ g_kw, const float* __restrict__ g_kb,
    const float* __restrict__ g_vw, const float* __restrict__ g_vb,
    const float* __restrict__ g_mlw, const float* __restrict__ g_mlb,
    const float* __restrict__ g_w1, const float* __restrict__ g_b1,
    const float* __restrict__ g_w2, const float* __restrict__ g_b2,
    const float* __restrict__ g_flw, const float* __restrict__ g_flb,
    float* __restrict__ g_out)
{
    __shared__ Smem sm;
    const int tid  = threadIdx.x;
    const int lane = tid & 31;
    const int warp = tid >> 5;

    // ---------------- global warp -> (row, tile) ----------------
    const unsigned g = (unsigned)blockIdx.x * WPB + warp;
    const unsigned row = g / WPR;
    const unsigned w   = g - row * WPR;
    const int istart = min((int)w * INT_W, SEQ - INT_W);
    const int s0 = istart - 8 + P * lane;

    // ---------------- load my 8 positions ----------------
    const float* xbase = g_x + (size_t)row * SEQ * D;
    float t[P * D];
    if (s0 >= 0 && s0 <= SEQ - P) {
        const float4* p = reinterpret_cast<const float4*>(xbase + (size_t)s0 * D);
#pragma unroll
        for (int k = 0; k < P * D / 4; k++) reinterpret_cast<float4*>(t)[k] = p[k];
    } else {
#pragma unroll
        for (int i = 0; i < P; i++) {
            int sc = min(max(s0 + i, 0), SEQ - 1);
            const float2* p = reinterpret_cast<const float2*>(xbase + (size_t)sc * D);
            float2 a0 = p[0], a1 = p[1], a2 = p[2];
            t[i * D + 0] = a0.x; t[i * D + 1] = a0.y; t[i * D + 2] = a1.x;
            t[i * D + 3] = a1.y; t[i * D + 4] = a2.x; t[i * D + 5] = a2.y;
        }
    }

    // ---------------- weight staging (packed broadcast pairs) ----------------
    for (int i = tid; i < L * DFF * D; i += TPB) {
        int l = i / (DFF * D), f = (i / D) % DFF, d = i % D;
        float v = g_w1[i];
        sm.w1p[l][f][d] = pk(v, v);
    }
    for (int i = tid; i < L * DFF; i += TPB) {
        float v = g_b1[i];
        sm.w1p[i / DFF][i % DFF][6] = pk(v, v);
    }
    for (int i = tid; i < L * D * DFF; i += TPB) {
        int l = i / (D * DFF), d = (i / DFF) % D, f = i % DFF;
        float v = g_w2[i];
        sm.w2p[l][f][d] = pk(v, v);
    }
    for (int i = tid; i < 2 * L * D; i += TPB) {
        int la = i / D, d = i % D;
        sm.attp[la][d][0] = pk(g_qw[i], g_qw[i]);
        sm.attp[la][d][1] = pk(g_qb[i], g_qb[i]);
        sm.attp[la][d][2] = pk(g_kw[i], g_kw[i]);
        sm.attp[la][d][3] = pk(g_kb[i], g_kb[i]);
        sm.attp[la][d][4] = pk(-g_vw[i], -g_vw[i]);   // negated
        sm.attp[la][d][5] = pk(-g_vb[i], -g_vb[i]);   // negated
        sm.attp[la][d][6] = pk(g_mlw[i], g_mlw[i]);
        sm.attp[la][d][7] = pk(g_mlb[i], g_mlb[i]);
    }
    for (int i = tid; i < L * D; i += TPB) {
        int l = i / D, d = i % D;
        sm.ffnlnp[l][0][d] = pk(g_flw[i], g_flw[i]);
        sm.ffnlnp[l][1][d] = pk(g_flb[i], g_flb[i]);
        sm.b2p[l][d] = pk(g_b2[i], g_b2[i]);
    }
    if (tid < D) {
        sm.decp[0][tid] = pk(g_dec_w[tid], g_dec_w[tid]);
        sm.decp[1][tid] = pk(g_dec_b[tid], g_dec_b[tid]);
    }
    __syncthreads();

    // ---------------- packed state: xp[j][d] = (pos 2j, pos 2j+1) ----------
    u64 xp[4][D];
#pragma unroll
    for (int j = 0; j < 4; j++)
#pragma unroll
        for (int d = 0; d < D; d++)
            xp[j][d] = pk(t[(2 * j) * D + d], t[(2 * j + 1) * D + d]);

#pragma unroll
    for (int j = 0; j < 4; j++) ln6p<1>(&xp[j][0], &sm.decp[0][0], &sm.decp[1][0]);

    const bool edgeL = (s0 == 0);
    const bool edgeR = (s0 == SEQ - P);
    const u64 INV2 = pk(INV_S, INV_S);

#pragma unroll 1
    for (int l = 0; l < L; l++) {
        // -------- two attention+LN stages --------
#pragma unroll
        for (int a = 0; a < 2; a++) {
            const int la = l * 2 + a;
#pragma unroll
            for (int d = 0; d < D; d++) {
                float2 p0 = up(xp[0][d]);
                float2 p1 = up(xp[1][d]);
                float2 p2 = up(xp[2][d]);
                float2 p3 = up(xp[3][d]);
                float xm1 = __shfl_up_sync(FULL, p3.y, 1);
                float xq1 = __shfl_down_sync(FULL, p0.x, 1);
                if (edgeL) xm1 = p0.x;
                if (edgeR) xq1 = p3.y;
                u64 l0 = pk(xm1, p0.x);
                u64 l1 = pk(p0.y, p1.x);   // also v-in for pair 0
                u64 l2 = pk(p1.y, p2.x);   // also v-in for pair 1
                u64 l3 = pk(p2.y, p3.x);   // also v-in for pair 2
                u64 r3 = pk(p3.y, xq1);    // v-in for pair 3
                const u64* wd = &sm.attp[la][d][0];
                ulonglong2 wq = *reinterpret_cast<const ulonglong2*>(wd + 0); // qw qb
                ulonglong2 wk = *reinterpret_cast<const ulonglong2*>(wd + 2); // kw kb
                ulonglong2 wv = *reinterpret_cast<const ulonglong2*>(wd + 4); // -vw -vb
                u64 q0 = f2fma(xp[0][d], wq.x, wq.y);
                u64 q1 = f2fma(xp[1][d], wq.x, wq.y);
                u64 q2 = f2fma(xp[2][d], wq.x, wq.y);
                u64 q3 = f2fma(xp[3][d], wq.x, wq.y);
                u64 k0 = f2fma(l0, wk.x, wk.y);
                u64 k1 = f2fma(l1, wk.x, wk.y);
                u64 k2 = f2fma(l2, wk.x, wk.y);
                u64 k3 = f2fma(l3, wk.x, wk.y);
                u64 n0 = f2fma(l1, wv.x, wv.y);   // -v
                u64 n1 = f2fma(l2, wv.x, wv.y);
                u64 n2 = f2fma(l3, wv.x, wv.y);
                u64 n3 = f2fma(r3, wv.x, wv.y);
                // teo = q^2 - k*v; x += teo/S with shallow x-chain
                u64 t0 = f2fma(q0, q0, f2mul(k0, n0));
                u64 t1 = f2fma(q1, q1, f2mul(k1, n1));
                u64 t2 = f2fma(q2, q2, f2mul(k2, n2));
                u64 t3 = f2fma(q3, q3, f2mul(k3, n3));
                xp[0][d] = f2fma(t0, INV2, xp[0][d]);
                xp[1][d] = f2fma(t1, INV2, xp[1][d]);
                xp[2][d] = f2fma(t2, INV2, xp[2][d]);
                xp[3][d] = f2fma(t3, INV2, xp[3][d]);
            }
#pragma unroll
            for (int j = 0; j < 4; j++)
                ln6p<8>(&xp[j][0], &sm.attp[la][0][6], &sm.attp[la][0][7]);
        }

        // -------- FFN: broadcast-LDS pair weights, 4 independent chains -----
        u64 y[4][D];
#pragma unroll
        for (int j = 0; j < 4; j++)
#pragma unroll
            for (int d = 0; d < D; d++)
                y[j][d] = f2add(xp[j][d], sm.b2p[l][d]);

        const u64* w1r = &sm.w1p[l][0][0];
        const u64* w2r = &sm.w2p[l][0][0];
#pragma unroll 4
        for (int f = 0; f < DFF; f++) {
            ulonglong2 wa = *reinterpret_cast<const ulonglong2*>(w1r + f * 8 + 0);
            ulonglong2 wb = *reinterpret_cast<const ulonglong2*>(w1r + f * 8 + 2);
            ulonglong2 wc = *reinterpret_cast<const ulonglong2*>(w1r + f * 8 + 4);
            u64 b1 = w1r[f * 8 + 6];
            u64 h0 = f2fma(xp[0][0], wa.x, b1);
            u64 h1 = f2fma(xp[1][0], wa.x, b1);
            u64 h2 = f2fma(xp[2][0], wa.x, b1);
            u64 h3 = f2fma(xp[3][0], wa.x, b1);
            h0 = f2fma(xp[0][1], wa.y, h0); h1 = f2fma(xp[1][1], wa.y, h1);
            h2 = f2fma(xp[2][1], wa.y, h2); h3 = f2fma(xp[3][1], wa.y, h3);
            h0 = f2fma(xp[0][2], wb.x, h0); h1 = f2fma(xp[1][2], wb.x, h1);
            h2 = f2fma(xp[2][2], wb.x, h2); h3 = f2fma(xp[3][2], wb.x, h3);
            h0 = f2fma(xp[0][3], wb.y, h0); h1 = f2fma(xp[1][3], wb.y, h1);
            h2 = f2fma(xp[2][3], wb.y, h2); h3 = f2fma(xp[3][3], wb.y, h3);
            h0 = f2fma(xp[0][4], wc.x, h0); h1 = f2fma(xp[1][4], wc.x, h1);
            h2 = f2fma(xp[2][4], wc.x, h2); h3 = f2fma(xp[3][4], wc.x, h3);
            h0 = f2fma(xp[0][5], wc.y, h0); h1 = f2fma(xp[1][5], wc.y, h1);
            h2 = f2fma(xp[2][5], wc.y, h2); h3 = f2fma(xp[3][5], wc.y, h3);
            h0 = relu2(h0); h1 = relu2(h1); h2 = relu2(h2); h3 = relu2(h3);
            ulonglong2 va = *reinterpret_cast<const ulonglong2*>(w2r + f * 8 + 0);
            ulonglong2 vb = *reinterpret_cast<const ulonglong2*>(w2r + f * 8 + 2);
            ulonglong2 vc = *reinterpret_cast<const ulonglong2*>(w2r + f * 8 + 4);
            y[0][0] = f2fma(h0, va.x, y[0][0]); y[1][0] = f2fma(h1, va.x, y[1][0]);
            y[2][0] = f2fma(h2, va.x, y[2][0]); y[3][0] = f2fma(h3, va.x, y[3][0]);
            y[0][1] = f2fma(h0, va.y, y[0][1]); y[1][1] = f2fma(h1, va.y, y[1][1]);
            y[2][1] = f2fma(h2, va.y, y[2][1]); y[3][1] = f2fma(h3, va.y, y[3][1]);
            y[0][2] = f2fma(h0, vb.x, y[0][2]); y[1][2] = f2fma(h1, vb.x, y[1][2]);
            y[2][2] = f2fma(h2, vb.x, y[2][2]); y[3][2] = f2fma(h3, vb.x, y[3][2]);
            y[0][3] = f2fma(h0, vb.y, y[0][3]); y[1][3] = f2fma(h1, vb.y, y[1][3]);
            y[2][3] = f2fma(h2, vb.y, y[2][3]); y[3][3] = f2fma(h3, vb.y, y[3][3]);
            y[0][4] = f2fma(h0, vc.x, y[0][4]); y[1][4] = f2fma(h1, vc.x, y[1][4]);
            y[2][4] = f2fma(h2, vc.x, y[2][4]); y[3][4] = f2fma(h3, vc.x, y[3][4]);
            y[0][5] = f2fma(h0, vc.y, y[0][5]); y[1][5] = f2fma(h1, vc.y, y[1][5]);
            y[2][5] = f2fma(h2, vc.y, y[2][5]); y[3][5] = f2fma(h3, vc.y, y[3][5]);
        }
#pragma unroll
        for (int j = 0; j < 4; j++) {
            ln6p<1>(&y[j][0], &sm.ffnlnp[l][0][0], &sm.ffnlnp[l][1][0]);
#pragma unroll
            for (int d = 0; d < D; d++) xp[j][d] = y[j][d];
        }
    }

    // ---------------- write interior (lanes 1..30) ----------------
    if (lane >= 1 && lane < 31) {
#pragma unroll
        for (int j = 0; j < 4; j++)
#pragma unroll
            for (int d = 0; d < D; d++) {
                float2 v = up(xp[j][d]);
                t[(2 * j) * D + d] = v.x;
                t[(2 * j + 1) * D + d] = v.y;
            }
        float4* o = reinterpret_cast<float4*>(g_out + ((size_t)row * SEQ + s0) * D);
#pragma unroll
        for (int k = 0; k < P * D / 4; k++) o[k] = reinterpret_cast<float4*>(t)[k];
    }
}

extern "C" void kernel_launch(void* const* d_in, const int* in_sizes, int n_in,
                              void* d_out, int out_size) {
    decoder_fused_kernel<<<NBLK, TPB>>>(
        (const float*)d_in[0],
        (const float*)d_in[2],  (const float*)d_in[3],
        (const float*)d_in[4],  (const float*)d_in[5],
        (const float*)d_in[6],  (const float*)d_in[7],
        (const float*)d_in[8],  (const float*)d_in[9],
        (const float*)d_in[12], (const float*)d_in[13],
        (const float*)d_in[14], (const float*)d_in[15],
        (const float*)d_in[16], (const float*)d_in[17],
        (const float*)d_in[18], (const float*)d_in[19],
        (float*)d_out);
}